// round 14
// baseline (speedup 1.0000x reference)
#include <cuda_runtime.h>
#include <cstdint>

// Problem constants
#define HD 128
#define FN 32
#define FE 16
#define KIN 48
#define DEPTH 3
#define MAXE 500000
#define MAXN 50000

// Scratch (device globals; no allocation allowed)
__device__ float g_h0[(size_t)MAXE * HD];
__device__ float g_hA[(size_t)MAXE * HD];
__device__ float g_hB[(size_t)MAXE * HD];
__device__ float g_amsg[(size_t)MAXN * HD];
// CSR (in-edges by col)
__device__ int g_deg[MAXN + 1];
__device__ int g_off[MAXN + 1];
__device__ int g_cursor[MAXN];
__device__ int g_perm[MAXE];
__device__ int g_bsum[64];

// ---------------------------------------------------------------------------
__global__ void k_init_out(float* __restrict__ out, const float* __restrict__ b_ffn, int G) {
    int t = blockIdx.x * blockDim.x + threadIdx.x;
    if (t < G) out[t] = b_ffn[0];
}

__global__ void k_zero_int2(int* __restrict__ a, int* __restrict__ b, int n) {
    int t = blockIdx.x * blockDim.x + threadIdx.x;
    if (t < n) { a[t] = 0; b[t] = 0; }
}

// ---------------------------------------------------------------------------
// CSR build
__global__ void k_count(const int* __restrict__ col, int* __restrict__ deg, int E) {
    int e = blockIdx.x * blockDim.x + threadIdx.x;
    if (e < E) atomicAdd(&deg[col[e]], 1);
}

__global__ void __launch_bounds__(256) k_scan1(
    const int* __restrict__ deg, int* __restrict__ off,
    int* __restrict__ bsum, int n)
{
    __shared__ int ws[8];
    const int tid = threadIdx.x;
    const int lane = tid & 31;
    const int w = tid >> 5;
    const int base = blockIdx.x * 1024 + tid * 4;

    int v0 = (base + 0 < n) ? deg[base + 0] : 0;
    int v1 = (base + 1 < n) ? deg[base + 1] : 0;
    int v2 = (base + 2 < n) ? deg[base + 2] : 0;
    int v3 = (base + 3 < n) ? deg[base + 3] : 0;
    int t = v0 + v1 + v2 + v3;

    int x = t;
#pragma unroll
    for (int d = 1; d < 32; d <<= 1) {
        int y = __shfl_up_sync(0xffffffffu, x, d);
        if (lane >= d) x += y;
    }
    if (lane == 31) ws[w] = x;
    __syncthreads();
    if (w == 0 && lane < 8) {
        int s = ws[lane];
#pragma unroll
        for (int d = 1; d < 8; d <<= 1) {
            int y = __shfl_up_sync(0xffu, s, d);
            if (lane >= d) s += y;
        }
        ws[lane] = s;
    }
    __syncthreads();

    int p = (x - t) + (w > 0 ? ws[w - 1] : 0);
    if (base + 0 < n) off[base + 0] = p; p += v0;
    if (base + 1 < n) off[base + 1] = p; p += v1;
    if (base + 2 < n) off[base + 2] = p; p += v2;
    if (base + 3 < n) off[base + 3] = p;
    if (tid == 0) bsum[blockIdx.x] = ws[7];
}

__global__ void k_scan2(int* __restrict__ bsum, int* __restrict__ off, int nb, int n) {
    if (threadIdx.x == 0 && blockIdx.x == 0) {
        int run = 0;
        for (int i = 0; i < nb; i++) {
            int v = bsum[i];
            bsum[i] = run;
            run += v;
        }
        off[n] = run;
    }
}

__global__ void __launch_bounds__(256) k_scan3(
    int* __restrict__ off, const int* __restrict__ bsum, int n)
{
    int add = bsum[blockIdx.x];
    int base = blockIdx.x * 1024 + threadIdx.x * 4;
#pragma unroll
    for (int q = 0; q < 4; q++)
        if (base + q < n) off[base + q] += add;
}

__global__ void k_fill(const int* __restrict__ col, const int* __restrict__ off,
                       int* __restrict__ cursor, int* __restrict__ perm, int E) {
    int e = blockIdx.x * blockDim.x + threadIdx.x;
    if (e < E) {
        int c = col[e];
        int r = atomicAdd(&cursor[c], 1);
        perm[off[c] + r] = e;
    }
}

// ---------------------------------------------------------------------------
// segment sum via CSR gather: amsg[n] = sum_{e in in(n)} h[e]   (no atomics)
__global__ void __launch_bounds__(256) k_gather(
    const float* __restrict__ h, const int* __restrict__ off,
    const int* __restrict__ perm, float* __restrict__ amsg, int N)
{
    const int warp = (blockIdx.x * blockDim.x + threadIdx.x) >> 5;
    const int lane = threadIdx.x & 31;
    if (warp >= N) return;
    const int s = off[warp];
    const int t = off[warp + 1];
    const float4* h4 = reinterpret_cast<const float4*>(h);
    float4 acc = make_float4(0.f, 0.f, 0.f, 0.f);
    for (int j = s; j < t; j++) {
        float4 v = h4[(size_t)perm[j] * 32 + lane];
        acc.x += v.x; acc.y += v.y; acc.z += v.z; acc.w += v.w;
    }
    reinterpret_cast<float4*>(amsg)[(size_t)warp * 32 + lane] = acc;
}

// ---------------------------------------------------------------------------
// edge init: h0[e] = relu(cat(x[row[e]], edge_attr[e]) @ W_init + b_init)
__global__ void __launch_bounds__(128) k_edge_init(
    const float* __restrict__ x, const float* __restrict__ ea,
    const int* __restrict__ row,
    const float* __restrict__ Wi, const float* __restrict__ bi,
    float* __restrict__ h0, float* __restrict__ h, int E)
{
    __shared__ float in_sm[8][KIN];
    const int j = threadIdx.x;
    float w[KIN];
#pragma unroll
    for (int k = 0; k < KIN; k++) w[k] = Wi[k * HD + j];
    const float bj = bi[j];

    for (int e0 = blockIdx.x * 8; e0 < E; e0 += gridDim.x * 8) {
        for (int idx = j; idx < 8 * KIN; idx += 128) {
            int i = idx / KIN, k = idx - i * KIN;
            int e = e0 + i;
            float v = 0.f;
            if (e < E) v = (k < FN) ? x[(size_t)row[e] * FN + k]
                                    : ea[(size_t)e * FE + (k - FN)];
            in_sm[i][k] = v;
        }
        __syncthreads();

        float acc[8];
#pragma unroll
        for (int i = 0; i < 8; i++) acc[i] = bj;
#pragma unroll
        for (int k = 0; k < KIN; k++) {
            float wv = w[k];
#pragma unroll
            for (int i = 0; i < 8; i++)
                acc[i] = fmaf(in_sm[i][k], wv, acc[i]);
        }
#pragma unroll
        for (int i = 0; i < 8; i++) {
            int e = e0 + i;
            if (e < E) {
                float r = fmaxf(acc[i], 0.f);
                h0[(size_t)e * HD + j] = r;
                h [(size_t)e * HD + j] = r;
            }
        }
        __syncthreads();
    }
}

// ---------------------------------------------------------------------------
// conv layer: HYBRID dual-pipe. Tile = 128 edges x 128 cols.
// warps 0-3: 3xTF32 mma.sync on edges [0,64)   (tensor pipe)
// warps 4-7: fp32 FFMA register tiles on edges [64,128)   (fma pipe)
#define A2_STRIDE 68
#define B2_STRIDE 136
#define OFF_A 0
#define OFF_B (128 * A2_STRIDE)
#define OFF_BIAS (128 * A2_STRIDE + 64 * B2_STRIDE)
#define MSM_TOTAL ((OFF_BIAS + 128) * 4)

__device__ __forceinline__ void mma_tf32(float& c0, float& c1, float& c2, float& c3,
                                         uint32_t a0, uint32_t a1, uint32_t a2, uint32_t a3,
                                         uint32_t b0, uint32_t b1) {
    asm volatile("mma.sync.aligned.m16n8k8.row.col.f32.tf32.tf32.f32 "
                 "{%0,%1,%2,%3}, {%4,%5,%6,%7}, {%8,%9}, {%0,%1,%2,%3};"
                 : "+f"(c0), "+f"(c1), "+f"(c2), "+f"(c3)
                 : "r"(a0), "r"(a1), "r"(a2), "r"(a3), "r"(b0), "r"(b1));
}

__device__ __forceinline__ void split_tf32(float v, uint32_t& hi, uint32_t& lo) {
    uint32_t h = __float_as_uint(v) & 0xFFFFE000u;
    hi = h;
    lo = __float_as_uint(v - __uint_as_float(h));
}

__global__ void __launch_bounds__(256, 2) k_conv_mma(
    const float* __restrict__ amsg, const float* __restrict__ h,
    const float* __restrict__ h0,
    const float* __restrict__ W, const float* __restrict__ b,
    const int* __restrict__ row, float* __restrict__ hout, int E)
{
    extern __shared__ float smf[];
    float* Asm = smf + OFF_A;
    float* Bsm = smf + OFF_B;
    float* bsm = smf + OFF_BIAS;

    const int tid = threadIdx.x;
    const int wid = tid >> 5;
    const int lid = tid & 31;

    if (tid < 128) bsm[tid] = b[tid];

    const int e0 = blockIdx.x << 7;
    const float4* amsg4 = reinterpret_cast<const float4*>(amsg);
    const float4* h4    = reinterpret_cast<const float4*>(h);

    // per-thread gather bases (2 threads per edge row; all 128 rows staged)
    const int r2 = tid >> 1;
    const int half = tid & 1;
    const int e_g = e0 + r2;
    const bool gvalid = (e_g < E);
    const float4* ap = nullptr;
    const float4* hp = nullptr;
    if (gvalid) {
        ap = amsg4 + (size_t)row[e_g] * 32 + half * 8;
        hp = h4 + (size_t)(e_g ^ 1) * 32 + half * 8;
    }

    // ---- mma lane mapping (warps 0-3: edges [0,64)) ----
    const int m0 = wid * 16;            // 0..48 for wid<4
    const int qr = lid >> 2;            // 0..7
    const int qc = lid & 3;             // 0..3
    float acc[16][4];
#pragma unroll
    for (int nb = 0; nb < 16; nb++)
#pragma unroll
        for (int q = 0; q < 4; q++) acc[nb][q] = 0.f;

    const float* a_lo_p = &Asm[(m0 + qr) * A2_STRIDE + qc];
    const float* a_hi_p = &Asm[(m0 + qr + 8) * A2_STRIDE + qc];
    const float* b_p    = &Bsm[qc * B2_STRIDE + qr];

    // ---- ffma lane mapping (warps 4-7: edges [64,128)) ----
    // warp fw handles 16 edges; lane: edge-group (lid&3)*4, col-group (lid>>2)*16
    const int febase = 64 + (wid - 4) * 16 + (lid & 3) * 4;   // local row
    const int fcg = (lid >> 2) * 16;                          // col base
    float facc[4][16];
#pragma unroll
    for (int i = 0; i < 4; i++)
#pragma unroll
        for (int c = 0; c < 16; c++) facc[i][c] = 0.f;

#pragma unroll
    for (int kc = 0; kc < 2; kc++) {
        // ---- stage A chunk (fp32): 64 k-values per row
        if (gvalid) {
            float* arow = &Asm[r2 * A2_STRIDE + half * 32];
            const float4* apc = ap + kc * 16;
            const float4* hpc = hp + kc * 16;
#pragma unroll
            for (int q = 0; q < 8; q++) {
                float4 a = apc[q];
                float4 hv = hpc[q];
                *reinterpret_cast<float4*>(&arow[q * 4]) =
                    make_float4(a.x - hv.x, a.y - hv.y, a.z - hv.z, a.w - hv.w);
            }
        }
        // ---- stage B chunk (fp32): W rows [kc*64, kc*64+64)
        {
            const float4* W4 = reinterpret_cast<const float4*>(W) + kc * 64 * 32;
            for (int idx = tid; idx < 64 * 32; idx += 256) {
                int k = idx >> 5, n4 = idx & 31;
                *reinterpret_cast<float4*>(&Bsm[k * B2_STRIDE + n4 * 4]) = W4[idx];
            }
        }
        __syncthreads();

        if (wid < 4) {
            // ---- tensor pipe: 3-term compensated tf32 mma over 64-K chunk
#pragma unroll
            for (int ks = 0; ks < 8; ks++) {
                const int k0 = ks * 8;
                uint32_t ah0, al0, ah1, al1, ah2, al2, ah3, al3;
                split_tf32(a_lo_p[k0],     ah0, al0);
                split_tf32(a_hi_p[k0],     ah1, al1);
                split_tf32(a_lo_p[k0 + 4], ah2, al2);
                split_tf32(a_hi_p[k0 + 4], ah3, al3);
                const float* bk = b_p + k0 * B2_STRIDE;
#pragma unroll
                for (int nb = 0; nb < 16; nb++) {
                    uint32_t bh0, bl0, bh1, bl1;
                    split_tf32(bk[nb * 8],                  bh0, bl0);
                    split_tf32(bk[4 * B2_STRIDE + nb * 8],  bh1, bl1);
                    mma_tf32(acc[nb][0], acc[nb][1], acc[nb][2], acc[nb][3],
                             al0, al1, al2, al3, bh0, bh1);
                    mma_tf32(acc[nb][0], acc[nb][1], acc[nb][2], acc[nb][3],
                             ah0, ah1, ah2, ah3, bl0, bl1);
                    mma_tf32(acc[nb][0], acc[nb][1], acc[nb][2], acc[nb][3],
                             ah0, ah1, ah2, ah3, bh0, bh1);
                }
            }
        } else {
            // ---- fma pipe: fp32 register outer-product over 64-K chunk
            const float* ar0 = &Asm[(febase + 0) * A2_STRIDE];
            const float* ar1 = &Asm[(febase + 1) * A2_STRIDE];
            const float* ar2 = &Asm[(febase + 2) * A2_STRIDE];
            const float* ar3 = &Asm[(febase + 3) * A2_STRIDE];
            const float* bb  = &Bsm[fcg];
#pragma unroll 4
            for (int k = 0; k < 64; k++) {
                float a0 = ar0[k], a1 = ar1[k], a2 = ar2[k], a3 = ar3[k];
                const float* bk = bb + k * B2_STRIDE;
                float4 b0 = *reinterpret_cast<const float4*>(bk);
                float4 b1 = *reinterpret_cast<const float4*>(bk + 4);
                float4 b2 = *reinterpret_cast<const float4*>(bk + 8);
                float4 b3 = *reinterpret_cast<const float4*>(bk + 12);
                float bv[16] = {b0.x, b0.y, b0.z, b0.w, b1.x, b1.y, b1.z, b1.w,
                                b2.x, b2.y, b2.z, b2.w, b3.x, b3.y, b3.z, b3.w};
#pragma unroll
                for (int c = 0; c < 16; c++) {
                    facc[0][c] = fmaf(a0, bv[c], facc[0][c]);
                    facc[1][c] = fmaf(a1, bv[c], facc[1][c]);
                    facc[2][c] = fmaf(a2, bv[c], facc[2][c]);
                    facc[3][c] = fmaf(a3, bv[c], facc[3][c]);
                }
            }
        }
        __syncthreads();
    }

    // ---- epilogues ----
    if (wid < 4) {
        const int ccol = qc * 2;
#pragma unroll
        for (int hrow = 0; hrow < 2; hrow++) {
            const int e = e0 + m0 + qr + hrow * 8;
            if (e < E) {
                const float* h0p = h0 + (size_t)e * HD;
                float* op = hout + (size_t)e * HD;
#pragma unroll
                for (int nb = 0; nb < 16; nb++) {
                    const int col = nb * 8 + ccol;
                    float2 hz = *reinterpret_cast<const float2*>(&h0p[col]);
                    float v0 = acc[nb][hrow * 2 + 0] + bsm[col]     + hz.x;
                    float v1 = acc[nb][hrow * 2 + 1] + bsm[col + 1] + hz.y;
                    float2 o = make_float2(fmaxf(v0, 0.f), fmaxf(v1, 0.f));
                    *reinterpret_cast<float2*>(&op[col]) = o;
                }
            }
        }
    } else {
#pragma unroll
        for (int i = 0; i < 4; i++) {
            const int e = e0 + febase + i;
            if (e < E) {
                const float* h0p = h0 + (size_t)e * HD + fcg;
                float* op = hout + (size_t)e * HD + fcg;
#pragma unroll
                for (int c4 = 0; c4 < 4; c4++) {
                    float4 hz = *reinterpret_cast<const float4*>(&h0p[c4 * 4]);
                    float4 bv = *reinterpret_cast<const float4*>(&bsm[fcg + c4 * 4]);
                    float4 o;
                    o.x = fmaxf(facc[i][c4 * 4 + 0] + bv.x + hz.x, 0.f);
                    o.y = fmaxf(facc[i][c4 * 4 + 1] + bv.y + hz.y, 0.f);
                    o.z = fmaxf(facc[i][c4 * 4 + 2] + bv.z + hz.z, 0.f);
                    o.w = fmaxf(facc[i][c4 * 4 + 3] + bv.w + hz.w, 0.f);
                    *reinterpret_cast<float4*>(&op[c4 * 4]) = o;
                }
            }
        }
    }
}

// ---------------------------------------------------------------------------
// node readout (unchanged)
__global__ void __launch_bounds__(256) k_node(
    const float* __restrict__ x, const float* __restrict__ s,
    const int* __restrict__ batch,
    const float* __restrict__ We, const float* __restrict__ be,
    const float* __restrict__ wffn, float* __restrict__ out, int N)
{
    __shared__ float in_sm[2][FN + HD];
    __shared__ float part[2][HD];
    __shared__ float redsm[2];
    const int t = threadIdx.x;
    const int j = t & 127;
    const int half = t >> 7;

    float w[80];
#pragma unroll
    for (int k = 0; k < 80; k++) w[k] = We[(half * 80 + k) * HD + j];
    const float bj = be[j];
    const float wf = wffn[j];

    for (int n0 = blockIdx.x * 2; n0 < N; n0 += gridDim.x * 2) {
        if (t < 2) redsm[t] = 0.f;
        for (int idx = t; idx < 2 * (FN + HD); idx += 256) {
            int i = idx / (FN + HD), k = idx - i * (FN + HD);
            int n = n0 + i;
            float v = 0.f;
            if (n < N) v = (k < FN) ? x[(size_t)n * FN + k]
                                    : s[(size_t)n * HD + (k - FN)];
            in_sm[i][k] = v;
        }
        __syncthreads();

        float a0 = 0.f, a1 = 0.f;
#pragma unroll
        for (int k = 0; k < 80; k++) {
            float wv = w[k];
            a0 = fmaf(in_sm[0][half * 80 + k], wv, a0);
            a1 = fmaf(in_sm[1][half * 80 + k], wv, a1);
        }
        if (half == 1) { part[0][j] = a0; part[1][j] = a1; }
        __syncthreads();

        if (half == 0) {
            float h0v = fmaxf(a0 + part[0][j] + bj, 0.f);
            float h1v = fmaxf(a1 + part[1][j] + bj, 0.f);
            float r0 = h0v * wf;
            float r1 = h1v * wf;
#pragma unroll
            for (int off = 16; off > 0; off >>= 1) {
                r0 += __shfl_down_sync(0xffffffffu, r0, off);
                r1 += __shfl_down_sync(0xffffffffu, r1, off);
            }
            if ((t & 31) == 0) {
                atomicAdd(&redsm[0], r0);
                atomicAdd(&redsm[1], r1);
            }
        }
        __syncthreads();
        if (t < 2) {
            int n = n0 + t;
            if (n < N) atomicAdd(&out[batch[n]], redsm[t]);
        }
        __syncthreads();
    }
}

// ---------------------------------------------------------------------------
extern "C" void kernel_launch(void* const* d_in, const int* in_sizes, int n_in,
                              void* d_out, int out_size)
{
    const float* x        = (const float*)d_in[0];
    const float* ea       = (const float*)d_in[1];
    const int*   eidx     = (const int*)  d_in[2];
    const int*   batch    = (const int*)  d_in[3];
    const float* W_init   = (const float*)d_in[4];
    const float* b_init   = (const float*)d_in[5];
    const float* W_convs  = (const float*)d_in[6];
    const float* b_convs  = (const float*)d_in[7];
    const float* W_e2n    = (const float*)d_in[8];
    const float* b_e2n    = (const float*)d_in[9];
    const float* W_ffn    = (const float*)d_in[10];
    const float* b_ffn    = (const float*)d_in[11];
    float* out = (float*)d_out;

    const int N = in_sizes[0] / FN;
    const int E = in_sizes[1] / FE;
    const int G = out_size;
    const int* row = eidx;
    const int* col = eidx + E;

    float* h0   = nullptr; cudaGetSymbolAddress((void**)&h0,   g_h0);
    float* hA   = nullptr; cudaGetSymbolAddress((void**)&hA,   g_hA);
    float* hB   = nullptr; cudaGetSymbolAddress((void**)&hB,   g_hB);
    float* amsg = nullptr; cudaGetSymbolAddress((void**)&amsg, g_amsg);
    int* deg    = nullptr; cudaGetSymbolAddress((void**)&deg,    g_deg);
    int* off    = nullptr; cudaGetSymbolAddress((void**)&off,    g_off);
    int* cursor = nullptr; cudaGetSymbolAddress((void**)&cursor, g_cursor);
    int* perm   = nullptr; cudaGetSymbolAddress((void**)&perm,   g_perm);
    int* bsum   = nullptr; cudaGetSymbolAddress((void**)&bsum,   g_bsum);

    cudaFuncSetAttribute(k_conv_mma, cudaFuncAttributeMaxDynamicSharedMemorySize, MSM_TOTAL);

    k_init_out<<<1, 128>>>(out, b_ffn, G);

    // ---- CSR build (once per launch; graph fixed) ----
    const int nb = (N + 1023) / 1024;
    k_zero_int2<<<(N + 255) / 256, 256>>>(deg, cursor, N);
    k_count<<<(E + 255) / 256, 256>>>(col, deg, E);
    k_scan1<<<nb, 256>>>(deg, off, bsum, N);
    k_scan2<<<1, 32>>>(bsum, off, nb, N);
    k_scan3<<<nb, 256>>>(off, bsum, N);
    k_fill<<<(E + 255) / 256, 256>>>(col, off, cursor, perm, E);

    const int egrid = (E + 7) / 8;
    k_edge_init<<<egrid, 128>>>(x, ea, row, W_init, b_init, h0, hA, E);

    const int ntiles = (E + 127) / 128;
    const int ggrid = (N + 7) / 8;

    float* hcur = hA;
    float* hnext = hB;
    for (int l = 0; l < DEPTH; l++) {
        k_gather<<<ggrid, 256>>>(hcur, off, perm, amsg, N);
        k_conv_mma<<<ntiles, 256, MSM_TOTAL>>>(amsg, hcur, h0,
                               W_convs + (size_t)l * HD * HD,
                               b_convs + (size_t)l * HD,
                               row, hnext, E);
        float* tmp = hcur; hcur = hnext; hnext = tmp;
    }

    k_gather<<<ggrid, 256>>>(hcur, off, perm, amsg, N);

    const int ngrid = (N + 1) / 2;
    k_node<<<ngrid, 256>>>(x, amsg, batch, W_e2n, b_e2n, W_ffn, out, N);
}

// round 15
// speedup vs baseline: 1.3023x; 1.3023x over previous
#include <cuda_runtime.h>
#include <cstdint>

// Problem constants
#define HD 128
#define FN 32
#define FE 16
#define KIN 48
#define DEPTH 3
#define MAXE 500000
#define MAXN 50000

// Scratch (device globals; no allocation allowed)
__device__ float g_h0[(size_t)MAXE * HD];
__device__ float g_hA[(size_t)MAXE * HD];
__device__ float g_hB[(size_t)MAXE * HD];
__device__ float g_amsg[(size_t)MAXN * HD];
// CSR (in-edges by col)
__device__ int g_deg[MAXN + 1];
__device__ int g_off[MAXN + 1];
__device__ int g_cursor[MAXN];
__device__ int g_perm[MAXE];
__device__ int g_bsum[64];

// ---------------------------------------------------------------------------
__global__ void k_init_out(float* __restrict__ out, const float* __restrict__ b_ffn, int G) {
    int t = blockIdx.x * blockDim.x + threadIdx.x;
    if (t < G) out[t] = b_ffn[0];
}

__global__ void k_zero_int2(int* __restrict__ a, int* __restrict__ b, int n) {
    int t = blockIdx.x * blockDim.x + threadIdx.x;
    if (t < n) { a[t] = 0; b[t] = 0; }
}

// ---------------------------------------------------------------------------
// CSR build
__global__ void k_count(const int* __restrict__ col, int* __restrict__ deg, int E) {
    int e = blockIdx.x * blockDim.x + threadIdx.x;
    if (e < E) atomicAdd(&deg[col[e]], 1);
}

__global__ void __launch_bounds__(256) k_scan1(
    const int* __restrict__ deg, int* __restrict__ off,
    int* __restrict__ bsum, int n)
{
    __shared__ int ws[8];
    const int tid = threadIdx.x;
    const int lane = tid & 31;
    const int w = tid >> 5;
    const int base = blockIdx.x * 1024 + tid * 4;

    int v0 = (base + 0 < n) ? deg[base + 0] : 0;
    int v1 = (base + 1 < n) ? deg[base + 1] : 0;
    int v2 = (base + 2 < n) ? deg[base + 2] : 0;
    int v3 = (base + 3 < n) ? deg[base + 3] : 0;
    int t = v0 + v1 + v2 + v3;

    int x = t;
#pragma unroll
    for (int d = 1; d < 32; d <<= 1) {
        int y = __shfl_up_sync(0xffffffffu, x, d);
        if (lane >= d) x += y;
    }
    if (lane == 31) ws[w] = x;
    __syncthreads();
    if (w == 0 && lane < 8) {
        int s = ws[lane];
#pragma unroll
        for (int d = 1; d < 8; d <<= 1) {
            int y = __shfl_up_sync(0xffu, s, d);
            if (lane >= d) s += y;
        }
        ws[lane] = s;
    }
    __syncthreads();

    int p = (x - t) + (w > 0 ? ws[w - 1] : 0);
    if (base + 0 < n) off[base + 0] = p; p += v0;
    if (base + 1 < n) off[base + 1] = p; p += v1;
    if (base + 2 < n) off[base + 2] = p; p += v2;
    if (base + 3 < n) off[base + 3] = p;
    if (tid == 0) bsum[blockIdx.x] = ws[7];
}

__global__ void k_scan2(int* __restrict__ bsum, int* __restrict__ off, int nb, int n) {
    if (threadIdx.x == 0 && blockIdx.x == 0) {
        int run = 0;
        for (int i = 0; i < nb; i++) {
            int v = bsum[i];
            bsum[i] = run;
            run += v;
        }
        off[n] = run;
    }
}

__global__ void __launch_bounds__(256) k_scan3(
    int* __restrict__ off, const int* __restrict__ bsum, int n)
{
    int add = bsum[blockIdx.x];
    int base = blockIdx.x * 1024 + threadIdx.x * 4;
#pragma unroll
    for (int q = 0; q < 4; q++)
        if (base + q < n) off[base + q] += add;
}

__global__ void k_fill(const int* __restrict__ col, const int* __restrict__ off,
                       int* __restrict__ cursor, int* __restrict__ perm, int E) {
    int e = blockIdx.x * blockDim.x + threadIdx.x;
    if (e < E) {
        int c = col[e];
        int r = atomicAdd(&cursor[c], 1);
        perm[off[c] + r] = e;
    }
}

// ---------------------------------------------------------------------------
// segment sum via CSR gather: amsg[n] = sum_{e in in(n)} h[e]   (no atomics)
__global__ void __launch_bounds__(256) k_gather(
    const float* __restrict__ h, const int* __restrict__ off,
    const int* __restrict__ perm, float* __restrict__ amsg, int N)
{
    const int warp = (blockIdx.x * blockDim.x + threadIdx.x) >> 5;
    const int lane = threadIdx.x & 31;
    if (warp >= N) return;
    const int s = off[warp];
    const int t = off[warp + 1];
    const float4* h4 = reinterpret_cast<const float4*>(h);
    float4 acc = make_float4(0.f, 0.f, 0.f, 0.f);
    for (int j = s; j < t; j++) {
        float4 v = h4[(size_t)perm[j] * 32 + lane];
        acc.x += v.x; acc.y += v.y; acc.z += v.z; acc.w += v.w;
    }
    reinterpret_cast<float4*>(amsg)[(size_t)warp * 32 + lane] = acc;
}

// ---------------------------------------------------------------------------
// edge init: h0[e] = relu(cat(x[row[e]], edge_attr[e]) @ W_init + b_init)
// (single write; layer 0 reads h0 for both the h and h0 roles)
__global__ void __launch_bounds__(128) k_edge_init(
    const float* __restrict__ x, const float* __restrict__ ea,
    const int* __restrict__ row,
    const float* __restrict__ Wi, const float* __restrict__ bi,
    float* __restrict__ h0, int E)
{
    __shared__ float in_sm[8][KIN];
    const int j = threadIdx.x;
    float w[KIN];
#pragma unroll
    for (int k = 0; k < KIN; k++) w[k] = Wi[k * HD + j];
    const float bj = bi[j];

    for (int e0 = blockIdx.x * 8; e0 < E; e0 += gridDim.x * 8) {
        for (int idx = j; idx < 8 * KIN; idx += 128) {
            int i = idx / KIN, k = idx - i * KIN;
            int e = e0 + i;
            float v = 0.f;
            if (e < E) v = (k < FN) ? x[(size_t)row[e] * FN + k]
                                    : ea[(size_t)e * FE + (k - FN)];
            in_sm[i][k] = v;
        }
        __syncthreads();

        float acc[8];
#pragma unroll
        for (int i = 0; i < 8; i++) acc[i] = bj;
#pragma unroll
        for (int k = 0; k < KIN; k++) {
            float wv = w[k];
#pragma unroll
            for (int i = 0; i < 8; i++)
                acc[i] = fmaf(in_sm[i][k], wv, acc[i]);
        }
#pragma unroll
        for (int i = 0; i < 8; i++) {
            int e = e0 + i;
            if (e < E)
                h0[(size_t)e * HD + j] = fmaxf(acc[i], 0.f);
        }
        __syncthreads();
    }
}

// ---------------------------------------------------------------------------
// conv layer via 3xTF32 mma.sync; fp32 operands in smem, hi/lo split in regs.
// (FROZEN round-9 config — all five perturbations measured slower)
// hout[e] = relu((amsg[row[e]] - h[e^1]) @ W + b + h0[e])
#define A2_STRIDE 68
#define B2_STRIDE 136
#define OFF_A 0
#define OFF_B (128 * A2_STRIDE)
#define OFF_BIAS (128 * A2_STRIDE + 64 * B2_STRIDE)
#define MSM_TOTAL ((OFF_BIAS + 128) * 4)

__device__ __forceinline__ void mma_tf32(float& c0, float& c1, float& c2, float& c3,
                                         uint32_t a0, uint32_t a1, uint32_t a2, uint32_t a3,
                                         uint32_t b0, uint32_t b1) {
    asm volatile("mma.sync.aligned.m16n8k8.row.col.f32.tf32.tf32.f32 "
                 "{%0,%1,%2,%3}, {%4,%5,%6,%7}, {%8,%9}, {%0,%1,%2,%3};"
                 : "+f"(c0), "+f"(c1), "+f"(c2), "+f"(c3)
                 : "r"(a0), "r"(a1), "r"(a2), "r"(a3), "r"(b0), "r"(b1));
}

__device__ __forceinline__ void split_tf32(float v, uint32_t& hi, uint32_t& lo) {
    uint32_t h = __float_as_uint(v) & 0xFFFFE000u;
    hi = h;
    lo = __float_as_uint(v - __uint_as_float(h));
}

__global__ void __launch_bounds__(256, 2) k_conv_mma(
    const float* __restrict__ amsg, const float* __restrict__ h,
    const float* __restrict__ h0,
    const float* __restrict__ W, const float* __restrict__ b,
    const int* __restrict__ row, float* __restrict__ hout, int E)
{
    extern __shared__ float smf[];
    float* Asm = smf + OFF_A;
    float* Bsm = smf + OFF_B;
    float* bsm = smf + OFF_BIAS;

    const int tid = threadIdx.x;
    const int wid = tid >> 5;
    const int lid = tid & 31;

    if (tid < 128) bsm[tid] = b[tid];

    const int e0 = blockIdx.x << 7;
    const float4* amsg4 = reinterpret_cast<const float4*>(amsg);
    const float4* h4    = reinterpret_cast<const float4*>(h);

    // per-thread gather bases (2 threads per edge row)
    const int r2 = tid >> 1;
    const int half = tid & 1;
    const int e_g = e0 + r2;
    const bool gvalid = (e_g < E);
    const float4* ap = nullptr;
    const float4* hp = nullptr;
    if (gvalid) {
        ap = amsg4 + (size_t)row[e_g] * 32 + half * 8;
        hp = h4 + (size_t)(e_g ^ 1) * 32 + half * 8;
    }

    // mma lane mapping
    const int m0 = wid * 16;
    const int qr = lid >> 2;        // 0..7
    const int qc = lid & 3;         // 0..3
    float acc[16][4];
#pragma unroll
    for (int nb = 0; nb < 16; nb++)
#pragma unroll
        for (int q = 0; q < 4; q++) acc[nb][q] = 0.f;

    const float* a_lo_p = &Asm[(m0 + qr) * A2_STRIDE + qc];
    const float* a_hi_p = &Asm[(m0 + qr + 8) * A2_STRIDE + qc];
    const float* b_p    = &Bsm[qc * B2_STRIDE + qr];

#pragma unroll
    for (int kc = 0; kc < 2; kc++) {
        // ---- stage A chunk (fp32): 64 k-values per row
        if (gvalid) {
            float* arow = &Asm[r2 * A2_STRIDE + half * 32];
            const float4* apc = ap + kc * 16;
            const float4* hpc = hp + kc * 16;
#pragma unroll
            for (int q = 0; q < 8; q++) {
                float4 a = apc[q];
                float4 hv = hpc[q];
                *reinterpret_cast<float4*>(&arow[q * 4]) =
                    make_float4(a.x - hv.x, a.y - hv.y, a.z - hv.z, a.w - hv.w);
            }
        }
        // ---- stage B chunk (fp32): W rows [kc*64, kc*64+64)
        {
            const float4* W4 = reinterpret_cast<const float4*>(W) + kc * 64 * 32;
            for (int idx = tid; idx < 64 * 32; idx += 256) {
                int k = idx >> 5, n4 = idx & 31;
                *reinterpret_cast<float4*>(&Bsm[k * B2_STRIDE + n4 * 4]) = W4[idx];
            }
        }
        __syncthreads();

        // ---- MMA over this 64-K chunk (3-term; splits in registers)
#pragma unroll
        for (int ks = 0; ks < 8; ks++) {
            const int k0 = ks * 8;
            uint32_t ah0, al0, ah1, al1, ah2, al2, ah3, al3;
            split_tf32(a_lo_p[k0],     ah0, al0);
            split_tf32(a_hi_p[k0],     ah1, al1);
            split_tf32(a_lo_p[k0 + 4], ah2, al2);
            split_tf32(a_hi_p[k0 + 4], ah3, al3);
            const float* bk = b_p + k0 * B2_STRIDE;
#pragma unroll
            for (int nb = 0; nb < 16; nb++) {
                uint32_t bh0, bl0, bh1, bl1;
                split_tf32(bk[nb * 8],                  bh0, bl0);
                split_tf32(bk[4 * B2_STRIDE + nb * 8],  bh1, bl1);
                // lo terms first, hi*hi last
                mma_tf32(acc[nb][0], acc[nb][1], acc[nb][2], acc[nb][3],
                         al0, al1, al2, al3, bh0, bh1);
                mma_tf32(acc[nb][0], acc[nb][1], acc[nb][2], acc[nb][3],
                         ah0, ah1, ah2, ah3, bl0, bl1);
                mma_tf32(acc[nb][0], acc[nb][1], acc[nb][2], acc[nb][3],
                         ah0, ah1, ah2, ah3, bh0, bh1);
            }
        }
        __syncthreads();
    }

    // epilogue
    {
        const int ccol = qc * 2;
#pragma unroll
        for (int hrow = 0; hrow < 2; hrow++) {
            const int e = e0 + m0 + qr + hrow * 8;
            if (e < E) {
                const float* h0p = h0 + (size_t)e * HD;
                float* op = hout + (size_t)e * HD;
#pragma unroll
                for (int nb = 0; nb < 16; nb++) {
                    const int col = nb * 8 + ccol;
                    float2 hz = *reinterpret_cast<const float2*>(&h0p[col]);
                    float v0 = acc[nb][hrow * 2 + 0] + bsm[col]     + hz.x;
                    float v1 = acc[nb][hrow * 2 + 1] + bsm[col + 1] + hz.y;
                    float2 o = make_float2(fmaxf(v0, 0.f), fmaxf(v1, 0.f));
                    *reinterpret_cast<float2*>(&op[col]) = o;
                }
            }
        }
    }
}

// ---------------------------------------------------------------------------
// node readout (unchanged)
__global__ void __launch_bounds__(256) k_node(
    const float* __restrict__ x, const float* __restrict__ s,
    const int* __restrict__ batch,
    const float* __restrict__ We, const float* __restrict__ be,
    const float* __restrict__ wffn, float* __restrict__ out, int N)
{
    __shared__ float in_sm[2][FN + HD];
    __shared__ float part[2][HD];
    __shared__ float redsm[2];
    const int t = threadIdx.x;
    const int j = t & 127;
    const int half = t >> 7;

    float w[80];
#pragma unroll
    for (int k = 0; k < 80; k++) w[k] = We[(half * 80 + k) * HD + j];
    const float bj = be[j];
    const float wf = wffn[j];

    for (int n0 = blockIdx.x * 2; n0 < N; n0 += gridDim.x * 2) {
        if (t < 2) redsm[t] = 0.f;
        for (int idx = t; idx < 2 * (FN + HD); idx += 256) {
            int i = idx / (FN + HD), k = idx - i * (FN + HD);
            int n = n0 + i;
            float v = 0.f;
            if (n < N) v = (k < FN) ? x[(size_t)n * FN + k]
                                    : s[(size_t)n * HD + (k - FN)];
            in_sm[i][k] = v;
        }
        __syncthreads();

        float a0 = 0.f, a1 = 0.f;
#pragma unroll
        for (int k = 0; k < 80; k++) {
            float wv = w[k];
            a0 = fmaf(in_sm[0][half * 80 + k], wv, a0);
            a1 = fmaf(in_sm[1][half * 80 + k], wv, a1);
        }
        if (half == 1) { part[0][j] = a0; part[1][j] = a1; }
        __syncthreads();

        if (half == 0) {
            float h0v = fmaxf(a0 + part[0][j] + bj, 0.f);
            float h1v = fmaxf(a1 + part[1][j] + bj, 0.f);
            float r0 = h0v * wf;
            float r1 = h1v * wf;
#pragma unroll
            for (int off = 16; off > 0; off >>= 1) {
                r0 += __shfl_down_sync(0xffffffffu, r0, off);
                r1 += __shfl_down_sync(0xffffffffu, r1, off);
            }
            if ((t & 31) == 0) {
                atomicAdd(&redsm[0], r0);
                atomicAdd(&redsm[1], r1);
            }
        }
        __syncthreads();
        if (t < 2) {
            int n = n0 + t;
            if (n < N) atomicAdd(&out[batch[n]], redsm[t]);
        }
        __syncthreads();
    }
}

// ---------------------------------------------------------------------------
extern "C" void kernel_launch(void* const* d_in, const int* in_sizes, int n_in,
                              void* d_out, int out_size)
{
    const float* x        = (const float*)d_in[0];
    const float* ea       = (const float*)d_in[1];
    const int*   eidx     = (const int*)  d_in[2];
    const int*   batch    = (const int*)  d_in[3];
    const float* W_init   = (const float*)d_in[4];
    const float* b_init   = (const float*)d_in[5];
    const float* W_convs  = (const float*)d_in[6];
    const float* b_convs  = (const float*)d_in[7];
    const float* W_e2n    = (const float*)d_in[8];
    const float* b_e2n    = (const float*)d_in[9];
    const float* W_ffn    = (const float*)d_in[10];
    const float* b_ffn    = (const float*)d_in[11];
    float* out = (float*)d_out;

    const int N = in_sizes[0] / FN;
    const int E = in_sizes[1] / FE;
    const int G = out_size;
    const int* row = eidx;
    const int* col = eidx + E;

    float* h0   = nullptr; cudaGetSymbolAddress((void**)&h0,   g_h0);
    float* hA   = nullptr; cudaGetSymbolAddress((void**)&hA,   g_hA);
    float* hB   = nullptr; cudaGetSymbolAddress((void**)&hB,   g_hB);
    float* amsg = nullptr; cudaGetSymbolAddress((void**)&amsg, g_amsg);
    int* deg    = nullptr; cudaGetSymbolAddress((void**)&deg,    g_deg);
    int* off    = nullptr; cudaGetSymbolAddress((void**)&off,    g_off);
    int* cursor = nullptr; cudaGetSymbolAddress((void**)&cursor, g_cursor);
    int* perm   = nullptr; cudaGetSymbolAddress((void**)&perm,   g_perm);
    int* bsum   = nullptr; cudaGetSymbolAddress((void**)&bsum,   g_bsum);

    cudaFuncSetAttribute(k_conv_mma, cudaFuncAttributeMaxDynamicSharedMemorySize, MSM_TOTAL);

    k_init_out<<<1, 128>>>(out, b_ffn, G);

    // ---- CSR build (once per launch; graph fixed) ----
    const int nb = (N + 1023) / 1024;
    k_zero_int2<<<(N + 255) / 256, 256>>>(deg, cursor, N);
    k_count<<<(E + 255) / 256, 256>>>(col, deg, E);
    k_scan1<<<nb, 256>>>(deg, off, bsum, N);
    k_scan2<<<1, 32>>>(bsum, off, nb, N);
    k_scan3<<<nb, 256>>>(off, bsum, N);
    k_fill<<<(E + 255) / 256, 256>>>(col, off, cursor, perm, E);

    const int egrid = (E + 7) / 8;
    k_edge_init<<<egrid, 128>>>(x, ea, row, W_init, b_init, h0, E);

    const int ntiles = (E + 127) / 128;
    const int ggrid = (N + 7) / 8;

    // buffer rotation: layer0 h = h0 (no duplicate copy), then hB -> hA -> hB
    float* hcur = h0;
    float* hnext = hB;
    for (int l = 0; l < DEPTH; l++) {
        k_gather<<<ggrid, 256>>>(hcur, off, perm, amsg, N);
        k_conv_mma<<<ntiles, 256, MSM_TOTAL>>>(amsg, hcur, h0,
                               W_convs + (size_t)l * HD * HD,
                               b_convs + (size_t)l * HD,
                               row, hnext, E);
        hcur = hnext;
        hnext = (hcur == hB) ? hA : hB;
    }

    k_gather<<<ggrid, 256>>>(hcur, off, perm, amsg, N);

    const int ngrid = (N + 1) / 2;
    k_node<<<ngrid, 256>>>(x, amsg, batch, W_e2n, b_e2n, W_ffn, out, N);
}